// round 16
// baseline (speedup 1.0000x reference)
#include <cuda_runtime.h>
#include <cuda_pipeline.h>
#include <cuda_fp16.h>
#include <mma.h>
#include <math.h>

using namespace nvcuda;

#define T_   64
#define B_   256
#define NIN_ 1024
#define H_   2048
#define G_   8192   // 4*H
#define BHALF 128   // batch rows per stream

// ---- scratch ----
__device__ float g_P[(size_t)T_ * B_ * G_];      // raw x@wx (pre-LN)
__device__ float g_HW[(size_t)B_ * G_];          // h@wh per step (no split)
__device__ float g_c[(size_t)B_ * H_];
__device__ __half g_hh[(size_t)B_ * H_];
__device__ __half g_hl[(size_t)B_ * H_];
__device__ __half g_xh[(size_t)T_ * B_ * NIN_];
__device__ __half g_xl[(size_t)T_ * B_ * NIN_];
__device__ __half g_wxh[(size_t)NIN_ * G_];
__device__ __half g_wxl[(size_t)NIN_ * G_];
__device__ __half g_whh[(size_t)H_ * G_];
__device__ __half g_whl[(size_t)H_ * G_];

// ============================================================
// Fused fp16x3 GEMM. One launch per (t, batch-half):
//   z=0: recurrent  h_half[128,H_] @ wh[H_,G_]   (K=2048)
//   z=1: xw slice   x_slice[128,NIN_] @ wx[NIN_,G_] (K=1024)
// Block 128x128, 8 warps (4x2), warp tile 32x64, BK=32,
// 3-stage cp.async, one __syncthreads per k-iter.
// ============================================================
#define GBM 128
#define GBN 128
#define GBK 32
#define ALD 40
#define BLD 136
#define NSTAGE 3
#define AS_H (GBM * ALD)
#define BS_H (GBK * BLD)
#define STAGE_H (2 * AS_H + 2 * BS_H)
#define SMEM_BYTES (STAGE_H * NSTAGE * 2)

__global__ __launch_bounds__(256, 2) void fused_gemm(
    const __half* __restrict__ Arec_h, const __half* __restrict__ Arec_l,
    const __half* __restrict__ Brec_h, const __half* __restrict__ Brec_l,
    const __half* __restrict__ Axw_h,  const __half* __restrict__ Axw_l,
    const __half* __restrict__ Bxw_h,  const __half* __restrict__ Bxw_l,
    float* __restrict__ Crec, float* __restrict__ Cxw)
{
    extern __shared__ __half smem[];

    const int tid = threadIdx.x;
    const int z = blockIdx.z;

    const __half *Abh, *Abl, *Bh_, *Bl_;
    float* Cc;
    int arsk, nit;
    if (z == 0) {
        Abh = Arec_h; Abl = Arec_l;
        Bh_ = Brec_h; Bl_ = Brec_l;
        Cc = Crec;    arsk = H_;    nit = H_ / GBK;     // 64
    } else {
        Abh = Axw_h;  Abl = Axw_l;
        Bh_ = Bxw_h;  Bl_ = Bxw_l;
        Cc = Cxw;     arsk = NIN_;  nit = NIN_ / GBK;   // 32
    }

    const __half* Bbh = Bh_ + (size_t)blockIdx.x * GBN;
    const __half* Bbl = Bl_ + (size_t)blockIdx.x * GBN;

    const int warp = tid >> 5;
    const int wm = warp & 3;
    const int wn = warp >> 2;

    wmma::fragment<wmma::accumulator, 16, 16, 16, float> acc[2][4];
    #pragma unroll
    for (int i = 0; i < 2; i++)
        #pragma unroll
        for (int j = 0; j < 4; j++)
            wmma::fill_fragment(acc[i][j], 0.0f);

    auto prefetch = [&](int it) {
        __half* s = smem + (size_t)(it % NSTAGE) * STAGE_H;
        __half* sAh = s;
        __half* sAl = s + AS_H;
        __half* sBh = s + 2 * AS_H;
        __half* sBl = s + 2 * AS_H + BS_H;
        const int k0 = it * GBK;
        #pragma unroll
        for (int q = 0; q < 2; q++) {
            int sa = tid * 2 + q;
            int r = sa >> 2, c = (sa & 3) * 8;
            __pipeline_memcpy_async(&sAh[r * ALD + c], Abh + (size_t)r * arsk + k0 + c, 16);
            __pipeline_memcpy_async(&sAl[r * ALD + c], Abl + (size_t)r * arsk + k0 + c, 16);
            int rb = sa >> 4, cb = (sa & 15) * 8;
            __pipeline_memcpy_async(&sBh[rb * BLD + cb], Bbh + (size_t)(k0 + rb) * G_ + cb, 16);
            __pipeline_memcpy_async(&sBl[rb * BLD + cb], Bbl + (size_t)(k0 + rb) * G_ + cb, 16);
        }
    };

    prefetch(0); __pipeline_commit();
    prefetch(1); __pipeline_commit();

    for (int it = 0; it < nit; ++it) {
        __pipeline_wait_prior((it + 1 < nit) ? 1 : 0);
        __syncthreads();

        if (it + 2 < nit) { prefetch(it + 2); __pipeline_commit(); }

        const __half* s = smem + (size_t)(it % NSTAGE) * STAGE_H;
        const __half* sAh = s;
        const __half* sAl = s + AS_H;
        const __half* sBh = s + 2 * AS_H;
        const __half* sBl = s + 2 * AS_H + BS_H;

        #pragma unroll
        for (int ks = 0; ks < GBK; ks += 16) {
            wmma::fragment<wmma::matrix_a, 16, 16, 16, __half, wmma::row_major> ah[2], al[2];
            #pragma unroll
            for (int i = 0; i < 2; i++) {
                wmma::load_matrix_sync(ah[i], &sAh[(wm * 32 + i * 16) * ALD + ks], ALD);
                wmma::load_matrix_sync(al[i], &sAl[(wm * 32 + i * 16) * ALD + ks], ALD);
            }
            #pragma unroll
            for (int j = 0; j < 4; j++) {
                const int colb = wn * 64 + j * 16;
                wmma::fragment<wmma::matrix_b, 16, 16, 16, __half, wmma::row_major> bf;
                wmma::load_matrix_sync(bf, &sBh[ks * BLD + colb], BLD);
                wmma::mma_sync(acc[0][j], al[0], bf, acc[0][j]);
                wmma::mma_sync(acc[1][j], al[1], bf, acc[1][j]);
                wmma::mma_sync(acc[0][j], ah[0], bf, acc[0][j]);
                wmma::mma_sync(acc[1][j], ah[1], bf, acc[1][j]);
                wmma::load_matrix_sync(bf, &sBl[ks * BLD + colb], BLD);
                wmma::mma_sync(acc[0][j], ah[0], bf, acc[0][j]);
                wmma::mma_sync(acc[1][j], ah[1], bf, acc[1][j]);
            }
        }
    }

    float* Cb = Cc + (size_t)(wm * 32) * G_
                   + (size_t)blockIdx.x * GBN + wn * 64;
    #pragma unroll
    for (int i = 0; i < 2; i++)
        #pragma unroll
        for (int j = 0; j < 4; j++)
            wmma::store_matrix_sync(Cb + (size_t)(i * 16) * G_ + j * 16,
                                    acc[i][j], G_, wmma::mem_row_major);
}

// ============================================================
__device__ __forceinline__ float fsigmoid(float x)
{
    return __fdividef(1.f, 1.f + __expf(-x));
}
__device__ __forceinline__ float ftanh(float x)
{
    return __fdividef(2.f, 1.f + __expf(-2.f * x)) - 1.f;
}

__global__ void split_kernel(const float* __restrict__ in,
                             __half* __restrict__ hi, __half* __restrict__ lo,
                             int n)
{
    int i = blockIdx.x * blockDim.x + threadIdx.x;
    if (i < n) {
        float v = in[i];
        __half h = __float2half_rn(v);
        hi[i] = h;
        lo[i] = __float2half_rn(v - __half2float(h));
    }
}

__device__ __forceinline__ void blk_reduce2_512(float& s, float& s2)
{
    __shared__ float rbuf[2][16];
    const int lane = threadIdx.x & 31;
    const int warp = threadIdx.x >> 5;
    #pragma unroll
    for (int o = 16; o; o >>= 1) {
        s  += __shfl_down_sync(0xffffffffu, s,  o);
        s2 += __shfl_down_sync(0xffffffffu, s2, o);
    }
    if (lane == 0) { rbuf[0][warp] = s; rbuf[1][warp] = s2; }
    __syncthreads();
    if (warp == 0) {
        s  = (lane < 16) ? rbuf[0][lane] : 0.f;
        s2 = (lane < 16) ? rbuf[1][lane] : 0.f;
        #pragma unroll
        for (int o = 8; o; o >>= 1) {
            s  += __shfl_down_sync(0xffffffffu, s,  o);
            s2 += __shfl_down_sync(0xffffffffu, s2, o);
        }
        if (lane == 0) { rbuf[0][0] = s; rbuf[1][0] = s2; }
    }
    __syncthreads();
    s  = rbuf[0][0];
    s2 = rbuf[1][0];
    __syncthreads();
}

__global__ void init_state_kernel(const float* __restrict__ init,
                                  const float* __restrict__ mask)
{
    int idx = blockIdx.x * blockDim.x + threadIdx.x;
    int b = idx >> 11;
    int j = idx & (H_ - 1);
    size_t base = (size_t)b * T_ * 2 * H_;
    g_c[idx] = init[base + j];
    float h = init[base + H_ + j] * (1.f - mask[b]);
    __half hh = __float2half_rn(h);
    g_hh[idx] = hh;
    g_hl[idx] = __float2half_rn(h - __half2float(hh));
}

// ============================================================
// Fused cell: both layernorms (raw P row + hw row), gates,
// c/h update. One batch half per launch (128 blocks x 512 thr).
// ============================================================
__global__ __launch_bounds__(512) void cell_kernel(
    int t, int b0, const float* __restrict__ mask,
    const float* __restrict__ P,
    const float* __restrict__ gx, const float* __restrict__ bx,
    const float* __restrict__ bvec,
    const float* __restrict__ gh, const float* __restrict__ bh,
    const float* __restrict__ gc, const float* __restrict__ bc,
    float* __restrict__ hs)
{
    const int b = blockIdx.x + b0;
    const int tid = threadIdx.x;
    const float keep = 1.f - mask[t * B_ + b];
    const float keep_next = (t + 1 < T_) ? (1.f - mask[(t + 1) * B_ + b]) : 1.f;
    const float* hw = g_HW + (size_t)b * G_;
    const float* p  = P + ((size_t)t * B_ + b) * G_;

    // pass 1: joint stats of hw row and P row
    float sH = 0.f, s2H = 0.f, sP = 0.f, s2P = 0.f;
    #pragma unroll
    for (int pp = 0; pp < G_ / (512 * 4); pp++) {
        int i4 = (tid + pp * 512) * 4;
        float4 hv = *(const float4*)(hw + i4);
        float4 pv = *(const float4*)(p + i4);
        sH  += hv.x + hv.y + hv.z + hv.w;
        s2H += hv.x * hv.x + hv.y * hv.y + hv.z * hv.z + hv.w * hv.w;
        sP  += pv.x + pv.y + pv.z + pv.w;
        s2P += pv.x * pv.x + pv.y * pv.y + pv.z * pv.z + pv.w * pv.w;
    }
    blk_reduce2_512(sH, s2H);
    blk_reduce2_512(sP, s2P);
    const float invG = 1.f / (float)G_;
    float muH   = sH * invG;
    float rstdH = rsqrtf(s2H * invG - muH * muH + 1e-5f);
    float muP   = sP * invG;
    float rstdP = rsqrtf(s2P * invG - muP * muP + 1e-5f);

    const int j0 = tid * 4;
    float cs = 0.f, cs2 = 0.f;
    float cn4[4], og4[4];
    {
        float z4[4][4];   // [gate][lane4]
        #pragma unroll
        for (int g = 0; g < 4; g++) {
            const size_t o = (size_t)g * H_ + j0;
            float4 hv  = *(const float4*)(hw + o);
            float4 pv  = *(const float4*)(p + o);
            float4 gx4 = *(const float4*)(gx + o);
            float4 bx4 = *(const float4*)(bx + o);
            float4 bb4 = *(const float4*)(bvec + o);
            float4 gh4 = *(const float4*)(gh + o);
            float4 bh4 = *(const float4*)(bh + o);
            z4[g][0] = (pv.x - muP) * rstdP * gx4.x + bx4.x + bb4.x + (hv.x - muH) * rstdH * gh4.x + bh4.x;
            z4[g][1] = (pv.y - muP) * rstdP * gx4.y + bx4.y + bb4.y + (hv.y - muH) * rstdH * gh4.y + bh4.y;
            z4[g][2] = (pv.z - muP) * rstdP * gx4.z + bx4.z + bb4.z + (hv.z - muH) * rstdH * gh4.z + bh4.z;
            z4[g][3] = (pv.w - muP) * rstdP * gx4.w + bx4.w + bb4.w + (hv.w - muH) * rstdH * gh4.w + bh4.w;
        }
        float4 cc = *(const float4*)(&g_c[(size_t)b * H_ + j0]);
        float cc_[4] = {cc.x, cc.y, cc.z, cc.w};
        #pragma unroll
        for (int q4 = 0; q4 < 4; q4++) {
            float ig = fsigmoid(z4[0][q4]);
            float fg = fsigmoid(z4[1][q4]);
            float og = fsigmoid(z4[2][q4]);
            float ug = ftanh(z4[3][q4]);
            float cn = fg * (cc_[q4] * keep) + ig * ug;
            cn4[q4] = cn;
            og4[q4] = og;
            cs += cn; cs2 += cn * cn;
        }
        *(float4*)(&g_c[(size_t)b * H_ + j0]) =
            make_float4(cn4[0], cn4[1], cn4[2], cn4[3]);
    }
    blk_reduce2_512(cs, cs2);
    const float invH = 1.f / (float)H_;
    float muc   = cs * invH;
    float rstdc = rsqrtf(cs2 * invH - muc * muc + 1e-5f);

    {
        float4 gc4 = *(const float4*)(gc + j0);
        float4 bc4 = *(const float4*)(bc + j0);
        float gc_[4] = {gc4.x, gc4.y, gc4.z, gc4.w};
        float bc_[4] = {bc4.x, bc4.y, bc4.z, bc4.w};
        float hn[4];
        __half hhp[4], hlp[4];
        #pragma unroll
        for (int q4 = 0; q4 < 4; q4++) {
            float v = og4[q4] * ftanh((cn4[q4] - muc) * rstdc * gc_[q4] + bc_[q4]);
            hn[q4] = v;
            float hm = v * keep_next;
            __half hhi = __float2half_rn(hm);
            hhp[q4] = hhi;
            hlp[q4] = __float2half_rn(hm - __half2float(hhi));
        }
        *(float4*)(hs + ((size_t)t * B_ + b) * H_ + j0) =
            make_float4(hn[0], hn[1], hn[2], hn[3]);
        __half2* ph = (__half2*)(&g_hh[(size_t)b * H_ + j0]);
        ph[0] = __halves2half2(hhp[0], hhp[1]);
        ph[1] = __halves2half2(hhp[2], hhp[3]);
        __half2* pl = (__half2*)(&g_hl[(size_t)b * H_ + j0]);
        pl[0] = __halves2half2(hlp[0], hlp[1]);
        pl[1] = __halves2half2(hlp[2], hlp[3]);
    }
}

__global__ void write_state_kernel(const float* __restrict__ hs,
                                   float* __restrict__ sout)
{
    int idx = blockIdx.x * blockDim.x + threadIdx.x;
    int b = idx >> 11;
    int j = idx & (H_ - 1);
    sout[(size_t)b * 2 * H_ + j] = g_c[idx];
    sout[(size_t)b * 2 * H_ + H_ + j] =
        hs[((size_t)(T_ - 1) * B_ + b) * H_ + j];
}

// ============================================================
extern "C" void kernel_launch(void* const* d_in, const int* in_sizes, int n_in,
                              void* d_out, int out_size)
{
    const float* x    = (const float*)d_in[0];
    const float* mask = (const float*)d_in[1];
    const float* init = (const float*)d_in[2];
    const float* wx   = (const float*)d_in[3];
    const float* wh   = (const float*)d_in[4];
    const float* bvec = (const float*)d_in[5];
    const float* gx   = (const float*)d_in[6];
    const float* bx   = (const float*)d_in[7];
    const float* gh   = (const float*)d_in[8];
    const float* bh   = (const float*)d_in[9];
    const float* gc   = (const float*)d_in[10];
    const float* bc   = (const float*)d_in[11];

    float* out  = (float*)d_out;
    float* hs   = out;
    float* sout = out + (size_t)T_ * B_ * H_;

    float *Pbuf, *HWbuf;
    __half *xh, *xl, *wxh, *wxl, *whh, *whl, *hh, *hl;
    cudaGetSymbolAddress((void**)&Pbuf,  g_P);
    cudaGetSymbolAddress((void**)&HWbuf, g_HW);
    cudaGetSymbolAddress((void**)&xh,    g_xh);
    cudaGetSymbolAddress((void**)&xl,    g_xl);
    cudaGetSymbolAddress((void**)&wxh,   g_wxh);
    cudaGetSymbolAddress((void**)&wxl,   g_wxl);
    cudaGetSymbolAddress((void**)&whh,   g_whh);
    cudaGetSymbolAddress((void**)&whl,   g_whl);
    cudaGetSymbolAddress((void**)&hh,    g_hh);
    cudaGetSymbolAddress((void**)&hl,    g_hl);

    cudaFuncSetAttribute(fused_gemm,
                         cudaFuncAttributeMaxDynamicSharedMemorySize, SMEM_BYTES);

    // prologue: splits + state init only
    {
        int nx = T_ * B_ * NIN_;
        split_kernel<<<(nx + 255) / 256, 256>>>(x, xh, xl, nx);
        int nwx = NIN_ * G_;
        split_kernel<<<(nwx + 255) / 256, 256>>>(wx, wxh, wxl, nwx);
        int nwh = H_ * G_;
        split_kernel<<<(nwh + 255) / 256, 256>>>(wh, whh, whl, nwh);
    }
    init_state_kernel<<<(B_ * H_) / 256, 256>>>(init, mask);

    cudaStream_t s1, s2;
    cudaStreamCreateWithFlags(&s1, cudaStreamNonBlocking);
    cudaStreamCreateWithFlags(&s2, cudaStreamNonBlocking);
    cudaEvent_t ev0, ev1, ev2;
    cudaEventCreateWithFlags(&ev0, cudaEventDisableTiming);
    cudaEventCreateWithFlags(&ev1, cudaEventDisableTiming);
    cudaEventCreateWithFlags(&ev2, cudaEventDisableTiming);

    cudaEventRecord(ev0, 0);
    cudaStreamWaitEvent(s1, ev0, 0);
    cudaStreamWaitEvent(s2, ev0, 0);

    for (int t = 0; t < T_; t++) {
        // half A (rows 0..127)
        {
            const size_t xo = ((size_t)t * B_ + 0) * NIN_;
            float* Po = Pbuf + ((size_t)t * B_ + 0) * G_;
            fused_gemm<<<dim3(G_ / GBN, 1, 2), 256, SMEM_BYTES, s1>>>(
                hh, hl, whh, whl,
                xh + xo, xl + xo, wxh, wxl,
                HWbuf, Po);
            cell_kernel<<<BHALF, 512, 0, s1>>>(
                t, 0, mask, Pbuf, gx, bx, bvec, gh, bh, gc, bc, hs);
        }
        // half B (rows 128..255)
        {
            const size_t xo = ((size_t)t * B_ + BHALF) * NIN_;
            float* Po = Pbuf + ((size_t)t * B_ + BHALF) * G_;
            fused_gemm<<<dim3(G_ / GBN, 1, 2), 256, SMEM_BYTES, s2>>>(
                hh + (size_t)BHALF * H_, hl + (size_t)BHALF * H_, whh, whl,
                xh + xo, xl + xo, wxh, wxl,
                HWbuf + (size_t)BHALF * G_, Po);
            cell_kernel<<<BHALF, 512, 0, s2>>>(
                t, BHALF, mask, Pbuf, gx, bx, bvec, gh, bh, gc, bc, hs);
        }
    }

    cudaEventRecord(ev1, s1);
    cudaEventRecord(ev2, s2);
    cudaStreamWaitEvent(0, ev1, 0);
    cudaStreamWaitEvent(0, ev2, 0);

    write_state_kernel<<<(B_ * H_) / 256, 256>>>(hs, sout);

    cudaEventDestroy(ev0);
    cudaEventDestroy(ev1);
    cudaEventDestroy(ev2);
    cudaStreamDestroy(s1);
    cudaStreamDestroy(s2);
}